// round 14
// baseline (speedup 1.0000x reference)
#include <cuda_runtime.h>
#include <cuda_fp16.h>
#include <math.h>
#include <cstdint>

// Problem constants
#define TT   2048
#define CC   1024
#define HH   4096
#define NE   8
#define NG   16
#define RCAP 3072
#define EPSN 1e-4f

// ---------------- device scratch ----------------
__device__ int    g_idx[TT];
__device__ float  g_score[TT];
__device__ int    g_counts[NE];
__device__ int    g_off[NE + 1];
__device__ int    g_perm[RCAP];
__device__ __half g_Xg[(size_t)RCAP * CC];   // row-major half (RN-rounded x)
__device__ __half g_H[(size_t)RCAP * HH];    // row-major half (GEMM1 output)

// ---------------- PTX helpers ----------------
#define CP16(dst, src) asm volatile("cp.async.cg.shared.global [%0], [%1], 16;" :: "r"(dst), "l"(src))
#define CPCOMMIT()     asm volatile("cp.async.commit_group;" ::: "memory")
#define CPWAIT2()      asm volatile("cp.async.wait_group 2;" ::: "memory")
#define CPWAIT4()      asm volatile("cp.async.wait_group 4;" ::: "memory")

__device__ __forceinline__ void ldsm_x4(uint32_t a, uint32_t& r0, uint32_t& r1,
                                        uint32_t& r2, uint32_t& r3) {
    asm volatile("ldmatrix.sync.aligned.m8n8.x4.shared.b16 {%0,%1,%2,%3}, [%4];"
        : "=r"(r0), "=r"(r1), "=r"(r2), "=r"(r3) : "r"(a));
}
__device__ __forceinline__ void ldsm_x2t(uint32_t a, uint32_t& r0, uint32_t& r1) {
    asm volatile("ldmatrix.sync.aligned.m8n8.x2.trans.shared.b16 {%0,%1}, [%2];"
        : "=r"(r0), "=r"(r1) : "r"(a));
}
__device__ __forceinline__ void mma_f16(float* c, const uint32_t* a, const uint32_t* b) {
    asm volatile("mma.sync.aligned.m16n8k16.row.col.f32.f16.f16.f32 "
        "{%0,%1,%2,%3}, {%4,%5,%6,%7}, {%8,%9}, {%0,%1,%2,%3};"
        : "+f"(c[0]), "+f"(c[1]), "+f"(c[2]), "+f"(c[3])
        : "r"(a[0]), "r"(a[1]), "r"(a[2]), "r"(a[3]), "r"(b[0]), "r"(b[1]));
}

// ---------------- kernel 0: gating ----------------
__global__ void gate_kernel(const float* __restrict__ x,
                            const float* __restrict__ wgred,
                            const float* __restrict__ wg) {
    __shared__ float s_unit[NE * NG];
    int warp = threadIdx.x >> 5;
    int lane = threadIdx.x & 31;
    if (threadIdx.x < NE) {
        float s = 0.f;
        #pragma unroll
        for (int g = 0; g < NG; g++) { float v = wg[threadIdx.x * NG + g]; s += v * v; }
        float nrm = fmaxf(sqrtf(s), EPSN);
        #pragma unroll
        for (int g = 0; g < NG; g++) s_unit[threadIdx.x * NG + g] = wg[threadIdx.x * NG + g] / nrm;
    }
    __syncthreads();

    int t = blockIdx.x * 8 + warp;
    const float* xr = x + (size_t)t * CC;
    float acc[NG];
    #pragma unroll
    for (int g = 0; g < NG; g++) acc[g] = 0.f;
    for (int c = lane; c < CC; c += 32) {
        float xv = xr[c];
        #pragma unroll
        for (int g = 0; g < NG; g++) acc[g] += xv * wgred[g * CC + c];
    }
    #pragma unroll
    for (int g = 0; g < NG; g++) {
        #pragma unroll
        for (int o = 16; o > 0; o >>= 1)
            acc[g] += __shfl_xor_sync(0xFFFFFFFFu, acc[g], o);
    }
    float logit = -1e30f;
    if (lane < NE) {
        float s = 0.f;
        #pragma unroll
        for (int g = 0; g < NG; g++) s += acc[g] * s_unit[lane * NG + g];
        logit = s;
    }
    float m = logit;
    #pragma unroll
    for (int o = 4; o > 0; o >>= 1) m = fmaxf(m, __shfl_xor_sync(0xFFFFFFFFu, m, o));
    int idxm = (lane < NE && logit == m) ? lane : NE;
    #pragma unroll
    for (int o = 4; o > 0; o >>= 1) idxm = min(idxm, __shfl_xor_sync(0xFFFFFFFFu, idxm, o));
    float ssum = (lane < NE) ? expf(logit - m) : 0.f;
    #pragma unroll
    for (int o = 4; o > 0; o >>= 1) ssum += __shfl_xor_sync(0xFFFFFFFFu, ssum, o);
    if (lane == 0) {
        g_idx[t]   = idxm;
        g_score[t] = 1.f / ssum;
    }
}

// ---------------- kernel 1: offsets + scatter (single block) ----------------
__global__ void offs_scatter_kernel() {
    __shared__ int hist[NE], sfill[NE], soff[NE];
    int tid = threadIdx.x;
    if (tid < NE) { hist[tid] = 0; sfill[tid] = 0; }
    __syncthreads();
    for (int t = tid; t < TT; t += 256) atomicAdd(&hist[g_idx[t]], 1);
    __syncthreads();
    if (tid == 0) {
        int o = 0;
        for (int e = 0; e < NE; e++) {
            g_off[e] = o; soff[e] = o;
            g_counts[e] = hist[e];
            o += (hist[e] + 127) & ~127;
        }
        g_off[NE] = o;
    }
    __syncthreads();
    for (int t = tid; t < TT; t += 256) {
        int e = g_idx[t];
        int p = soff[e] + atomicAdd(&sfill[e], 1);
        g_perm[p] = t;
    }
}

// ---------------- kernel 2: gather x -> half rows ----------------
__global__ void gather_kernel(const float* __restrict__ x) {
    int r = blockIdx.x;
    int e = 0;
    #pragma unroll
    for (int i = 1; i < NE; i++) if (r >= g_off[i]) e = i;
    bool valid = (r - g_off[e]) < g_counts[e];
    int k = threadIdx.x * 4;
    __half2 h0 = __floats2half2_rn(0.f, 0.f), h1 = h0;
    if (valid) {
        int t = g_perm[r];
        float4 v = *(const float4*)(x + (size_t)t * CC + k);
        h0 = __floats2half2_rn(v.x, v.y);
        h1 = __floats2half2_rn(v.z, v.w);
    }
    uint2 pk = make_uint2(*(uint32_t*)&h0, *(uint32_t*)&h1);
    *(uint2*)(g_Xg + (size_t)r * CC + k) = pk;
}

// ---------------- fp16 mma grouped GEMM ----------------
// CTA tile 128x128, 256 threads, 8 warps (2m x 4n), warp 64x32, BK=32, 3-stage.
// B path = cp.async fp32 staging -> smem cvt -> fp16 tile.
// NSPLIT: split-K factor (blockIdx.z); MODE 1 epilogue atomicAdds partials.
#define ASTRH 40      // A smem row stride in halves (32+8)
#define BSTRH 136     // B fp16 smem row stride in halves (128+8)

template<int KTOT, int LDB, int MODE, int NSPLIT>
__global__ __launch_bounds__(256, 2)
void gemm_mma(const float* __restrict__ Bw, const float* __restrict__ bias,
              float* __restrict__ outp) {
    constexpr int BM  = 128;
    constexpr int BK  = 32;
    constexpr int KLOC = KTOT / NSPLIT;
    constexpr int NKC = KLOC / BK;
    constexpr int MI  = 4;
    constexpr int NI  = 4;
    constexpr int AB  = BM * ASTRH * 2;
    constexpr int BHB = 32 * BSTRH * 2;
    constexpr int BFB = 32 * 128 * 4;
    constexpr int A_OFF  = 0;
    constexpr int BH_OFF = 3 * AB;
    constexpr int BF_OFF = BH_OFF + 3 * BHB;

    extern __shared__ char smem[];
    int tid = threadIdx.x, lane = tid & 31, wid = tid >> 5;
    int wm0 = (wid & 1) * 64;
    int wn0 = (wid >> 1) * 32;

    int m0 = blockIdx.x * BM;
    int n0 = blockIdx.y * 128;
    int ksp = (NSPLIT > 1) ? blockIdx.z : 0;
    if (m0 >= g_off[NE]) return;
    int e = 0;
    #pragma unroll
    for (int i = 1; i < NE; i++) if (m0 >= g_off[i]) e = i;
    if (m0 >= g_off[e] + g_counts[e]) return;

    const __half* Abase = ((MODE == 0) ? g_Xg : g_H)
                        + (size_t)m0 * KTOT + ksp * KLOC;
    const float*  Bbase = Bw + (size_t)e * KTOT * LDB
                        + (size_t)(ksp * KLOC) * LDB + n0;

    uint32_t sbase = (uint32_t)__cvta_generic_to_shared(smem);

    auto cpA = [&](int stg, int k0) {
        uint32_t sA = sbase + (uint32_t)(A_OFF + stg * AB);
        #pragma unroll
        for (int it = 0; it < 2; it++) {
            int idx = it * 256 + tid;
            int r = idx >> 2, j = idx & 3;
            CP16(sA + (uint32_t)(r * ASTRH + j * 8) * 2u,
                 Abase + (size_t)r * KTOT + k0 + j * 8);
        }
    };
    auto cpBf = [&](int stg, int k0) {
        uint32_t sF = sbase + (uint32_t)(BF_OFF + stg * BFB);
        #pragma unroll
        for (int it = 0; it < 4; it++) {
            int idx = it * 256 + tid;
            int k = idx >> 5, c = idx & 31;
            CP16(sF + (uint32_t)(k * 128 + c * 4) * 4u,
                 Bbase + (size_t)(k0 + k) * LDB + c * 4);
        }
    };
    auto cvtB = [&](int stg) {
        const float* src = (const float*)(smem + BF_OFF + stg * BFB);
        __half* dst = (__half*)(smem + BH_OFF + stg * BHB);
        #pragma unroll
        for (int it = 0; it < 4; it++) {
            int idx = it * 256 + tid;
            int k = idx >> 5, c = idx & 31;
            float4 v = *(const float4*)(src + k * 128 + c * 4);
            __half2 h0 = __floats2half2_rn(v.x, v.y);
            __half2 h1 = __floats2half2_rn(v.z, v.w);
            *(uint2*)(dst + k * BSTRH + c * 4) =
                make_uint2(*(uint32_t*)&h0, *(uint32_t*)&h1);
        }
    };

    float acc[MI][NI][4];
    #pragma unroll
    for (int mi = 0; mi < MI; mi++)
        #pragma unroll
        for (int ni = 0; ni < NI; ni++)
            #pragma unroll
            for (int q = 0; q < 4; q++) acc[mi][ni][q] = 0.f;

    uint32_t aoff[MI], boff;
    #pragma unroll
    for (int mi = 0; mi < MI; mi++)
        aoff[mi] = (uint32_t)((wm0 + mi * 16 + (lane & 15)) * ASTRH) * 2u
                 + (uint32_t)((lane >> 4) * 16);
    boff = (uint32_t)((lane & 15) * BSTRH) * 2u + (uint32_t)(wn0 * 2);

    // prologue: groups [Bf0][A0][Bf1][A1][Bf2]; then Bh(0) ready
    cpBf(0, 0);        CPCOMMIT();
    cpA(0, 0);         CPCOMMIT();
    cpBf(1, BK);       CPCOMMIT();
    cpA(1, BK);        CPCOMMIT();
    cpBf(2, 2 * BK);   CPCOMMIT();
    CPWAIT4();
    __syncthreads();
    cvtB(0);

    for (int i = 0; i < NKC; i++) {
        CPWAIT2();                    // drains A(i) and Bf(i+1)
        __syncthreads();              // visibility + ring-slot drain
        if (i + 1 < NKC) cvtB((i + 1) % 3);
        if (i + 3 < NKC) cpBf((i + 3) % 3, (i + 3) * BK);
        CPCOMMIT();
        if (i + 2 < NKC) cpA((i + 2) % 3, (i + 2) * BK);
        CPCOMMIT();

        uint32_t sA  = sbase + (uint32_t)(A_OFF + (i % 3) * AB);
        uint32_t sBh = sbase + (uint32_t)(BH_OFF + (i % 3) * BHB);
        #pragma unroll
        for (int ks = 0; ks < 2; ks++) {
            uint32_t af[MI][4], bf[NI][2];
            #pragma unroll
            for (int mi = 0; mi < MI; mi++)
                ldsm_x4(sA + aoff[mi] + (uint32_t)(ks * 32),
                        af[mi][0], af[mi][1], af[mi][2], af[mi][3]);
            #pragma unroll
            for (int ni = 0; ni < NI; ni++)
                ldsm_x2t(sBh + boff + (uint32_t)(ks * 16 * BSTRH * 2 + ni * 16),
                         bf[ni][0], bf[ni][1]);
            #pragma unroll
            for (int mi = 0; mi < MI; mi++)
                #pragma unroll
                for (int ni = 0; ni < NI; ni++)
                    mma_f16(acc[mi][ni], af[mi], bf[ni]);
        }
    }

    // ---------------- epilogue ----------------
    #pragma unroll
    for (int mi = 0; mi < MI; mi++) {
        int r0 = m0 + wm0 + mi * 16 + (lane >> 2);
        int tok0 = -1, tok1 = -1; float sc0 = 0.f, sc1 = 0.f;
        if (MODE == 1) {
            if ((r0 - g_off[e]) < g_counts[e])     { tok0 = g_perm[r0];     sc0 = g_score[tok0]; }
            if ((r0 + 8 - g_off[e]) < g_counts[e]) { tok1 = g_perm[r0 + 8]; sc1 = g_score[tok1]; }
        }
        #pragma unroll
        for (int ni = 0; ni < NI; ni++) {
            int c = n0 + wn0 + ni * 8 + ((lane & 3) << 1);
            float bsv0 = (MODE == 1 && ksp != 0) ? 0.f : bias[(size_t)e * LDB + c];
            float bsv1 = (MODE == 1 && ksp != 0) ? 0.f : bias[(size_t)e * LDB + c + 1];
            if (MODE == 0) {
                float v0 = acc[mi][ni][0] + bsv0;
                float v1 = acc[mi][ni][1] + bsv1;
                float v2 = acc[mi][ni][2] + bsv0;
                float v3 = acc[mi][ni][3] + bsv1;
                v0 = 0.5f * v0 * (1.0f + erff(v0 * 0.70710678118654752f));
                v1 = 0.5f * v1 * (1.0f + erff(v1 * 0.70710678118654752f));
                v2 = 0.5f * v2 * (1.0f + erff(v2 * 0.70710678118654752f));
                v3 = 0.5f * v3 * (1.0f + erff(v3 * 0.70710678118654752f));
                __half2 h01 = __floats2half2_rn(v0, v1);
                __half2 h23 = __floats2half2_rn(v2, v3);
                *(uint32_t*)(g_H + (size_t)r0 * HH + c)       = *(uint32_t*)&h01;
                *(uint32_t*)(g_H + (size_t)(r0 + 8) * HH + c) = *(uint32_t*)&h23;
            } else {
                if (tok0 >= 0) {
                    atomicAdd(outp + (size_t)tok0 * CC + c,     (acc[mi][ni][0] + bsv0) * sc0);
                    atomicAdd(outp + (size_t)tok0 * CC + c + 1, (acc[mi][ni][1] + bsv1) * sc0);
                }
                if (tok1 >= 0) {
                    atomicAdd(outp + (size_t)tok1 * CC + c,     (acc[mi][ni][2] + bsv0) * sc1);
                    atomicAdd(outp + (size_t)tok1 * CC + c + 1, (acc[mi][ni][3] + bsv1) * sc1);
                }
            }
        }
    }
}

// smem bytes: 3*(A + Bh + Bf32)
#define SMEMSZ (3 * (128 * ASTRH * 2 + 32 * BSTRH * 2 + 32 * 128 * 4))   // 105984

// ---------------- launch ----------------
extern "C" void kernel_launch(void* const* d_in, const int* in_sizes, int n_in,
                              void* d_out, int out_size) {
    const float* x      = (const float*)d_in[0];
    const float* wg_red = (const float*)d_in[1];
    const float* wg     = (const float*)d_in[2];
    const float* w1     = (const float*)d_in[3];
    const float* b1     = (const float*)d_in[4];
    const float* w2     = (const float*)d_in[5];
    const float* b2     = (const float*)d_in[6];
    float* out = (float*)d_out;

    cudaFuncSetAttribute(gemm_mma<CC, HH, 0, 1>,
                         cudaFuncAttributeMaxDynamicSharedMemorySize, SMEMSZ);
    cudaFuncSetAttribute(gemm_mma<HH, CC, 1, 2>,
                         cudaFuncAttributeMaxDynamicSharedMemorySize, SMEMSZ);

    gate_kernel<<<TT / 8, 256>>>(x, wg_red, wg);          // launch 0
    offs_scatter_kernel<<<1, 256>>>();                    // launch 1
    gather_kernel<<<RCAP, 256>>>(x);                      // launch 2
    gemm_mma<CC, HH, 0, 1>                                // launch 3 <- ncu lands here
        <<<dim3(RCAP / 128, HH / 128), 256, SMEMSZ>>>(w1, b1, nullptr);
    cudaMemsetAsync(out, 0, (size_t)TT * CC * sizeof(float));
    gemm_mma<HH, CC, 1, 2>                                // split-K = 2
        <<<dim3(RCAP / 128, CC / 128, 2), 256, SMEMSZ>>>(w2, b2, out);
}

// round 15
// speedup vs baseline: 1.1051x; 1.1051x over previous
#include <cuda_runtime.h>
#include <cuda_fp16.h>
#include <math.h>
#include <cstdint>

// Problem constants
#define TT   2048
#define CC   1024
#define HH   4096
#define NE   8
#define NG   16
#define RCAP 3072
#define EPSN 1e-4f

// ---------------- device scratch ----------------
__device__ int    g_idx[TT];
__device__ float  g_score[TT];
__device__ int    g_counts[NE];
__device__ int    g_off[NE + 1];
__device__ int    g_perm[RCAP];
__device__ __half g_Xg[(size_t)RCAP * CC];
__device__ __half g_H[(size_t)RCAP * HH];

// ---------------- PTX helpers ----------------
#define CP16(dst, src) asm volatile("cp.async.cg.shared.global [%0], [%1], 16;" :: "r"(dst), "l"(src))
#define CPCOMMIT()     asm volatile("cp.async.commit_group;" ::: "memory")
#define CPWAIT1()      asm volatile("cp.async.wait_group 1;" ::: "memory")
#define CPWAIT2()      asm volatile("cp.async.wait_group 2;" ::: "memory")
#define CPWAIT4()      asm volatile("cp.async.wait_group 4;" ::: "memory")

__device__ __forceinline__ void ldsm_x4(uint32_t a, uint32_t& r0, uint32_t& r1,
                                        uint32_t& r2, uint32_t& r3) {
    asm volatile("ldmatrix.sync.aligned.m8n8.x4.shared.b16 {%0,%1,%2,%3}, [%4];"
        : "=r"(r0), "=r"(r1), "=r"(r2), "=r"(r3) : "r"(a));
}
__device__ __forceinline__ void ldsm_x2t(uint32_t a, uint32_t& r0, uint32_t& r1) {
    asm volatile("ldmatrix.sync.aligned.m8n8.x2.trans.shared.b16 {%0,%1}, [%2];"
        : "=r"(r0), "=r"(r1) : "r"(a));
}
__device__ __forceinline__ void mma_f16(float* c, const uint32_t* a, const uint32_t* b) {
    asm volatile("mma.sync.aligned.m16n8k16.row.col.f32.f16.f16.f32 "
        "{%0,%1,%2,%3}, {%4,%5,%6,%7}, {%8,%9}, {%0,%1,%2,%3};"
        : "+f"(c[0]), "+f"(c[1]), "+f"(c[2]), "+f"(c[3])
        : "r"(a[0]), "r"(a[1]), "r"(a[2]), "r"(a[3]), "r"(b[0]), "r"(b[1]));
}
#define STS64(addr, u0, u1) \
    asm volatile("st.shared.v2.b32 [%0], {%1,%2};" :: "r"(addr), "r"(u0), "r"(u1))

// ---------------- kernel 0: gating ----------------
__global__ void gate_kernel(const float* __restrict__ x,
                            const float* __restrict__ wgred,
                            const float* __restrict__ wg) {
    __shared__ float s_unit[NE * NG];
    int warp = threadIdx.x >> 5;
    int lane = threadIdx.x & 31;
    if (threadIdx.x < NE) {
        float s = 0.f;
        #pragma unroll
        for (int g = 0; g < NG; g++) { float v = wg[threadIdx.x * NG + g]; s += v * v; }
        float nrm = fmaxf(sqrtf(s), EPSN);
        #pragma unroll
        for (int g = 0; g < NG; g++) s_unit[threadIdx.x * NG + g] = wg[threadIdx.x * NG + g] / nrm;
    }
    __syncthreads();

    int t = blockIdx.x * 8 + warp;
    const float* xr = x + (size_t)t * CC;
    float acc[NG];
    #pragma unroll
    for (int g = 0; g < NG; g++) acc[g] = 0.f;
    for (int c = lane; c < CC; c += 32) {
        float xv = xr[c];
        #pragma unroll
        for (int g = 0; g < NG; g++) acc[g] += xv * wgred[g * CC + c];
    }
    #pragma unroll
    for (int g = 0; g < NG; g++) {
        #pragma unroll
        for (int o = 16; o > 0; o >>= 1)
            acc[g] += __shfl_xor_sync(0xFFFFFFFFu, acc[g], o);
    }
    float logit = -1e30f;
    if (lane < NE) {
        float s = 0.f;
        #pragma unroll
        for (int g = 0; g < NG; g++) s += acc[g] * s_unit[lane * NG + g];
        logit = s;
    }
    float m = logit;
    #pragma unroll
    for (int o = 4; o > 0; o >>= 1) m = fmaxf(m, __shfl_xor_sync(0xFFFFFFFFu, m, o));
    int idxm = (lane < NE && logit == m) ? lane : NE;
    #pragma unroll
    for (int o = 4; o > 0; o >>= 1) idxm = min(idxm, __shfl_xor_sync(0xFFFFFFFFu, idxm, o));
    float ssum = (lane < NE) ? expf(logit - m) : 0.f;
    #pragma unroll
    for (int o = 4; o > 0; o >>= 1) ssum += __shfl_xor_sync(0xFFFFFFFFu, ssum, o);
    if (lane == 0) {
        g_idx[t]   = idxm;
        g_score[t] = 1.f / ssum;
    }
}

// ---------------- kernel 1: offsets + scatter (single block) ----------------
__global__ void offs_scatter_kernel() {
    __shared__ int hist[NE], sfill[NE], soff[NE];
    int tid = threadIdx.x;
    if (tid < NE) { hist[tid] = 0; sfill[tid] = 0; }
    __syncthreads();
    for (int t = tid; t < TT; t += 256) atomicAdd(&hist[g_idx[t]], 1);
    __syncthreads();
    if (tid == 0) {
        int o = 0;
        for (int e = 0; e < NE; e++) {
            g_off[e] = o; soff[e] = o;
            g_counts[e] = hist[e];
            o += (hist[e] + 127) & ~127;
        }
        g_off[NE] = o;
    }
    __syncthreads();
    for (int t = tid; t < TT; t += 256) {
        int e = g_idx[t];
        int p = soff[e] + atomicAdd(&sfill[e], 1);
        g_perm[p] = t;
    }
}

// ---------------- kernel 2: gather x -> half rows ----------------
__global__ void gather_kernel(const float* __restrict__ x) {
    int r = blockIdx.x;
    int e = 0;
    #pragma unroll
    for (int i = 1; i < NE; i++) if (r >= g_off[i]) e = i;
    bool valid = (r - g_off[e]) < g_counts[e];
    int k = threadIdx.x * 4;
    __half2 h0 = __floats2half2_rn(0.f, 0.f), h1 = h0;
    if (valid) {
        int t = g_perm[r];
        float4 v = *(const float4*)(x + (size_t)t * CC + k);
        h0 = __floats2half2_rn(v.x, v.y);
        h1 = __floats2half2_rn(v.z, v.w);
    }
    uint2 pk = make_uint2(*(uint32_t*)&h0, *(uint32_t*)&h1);
    *(uint2*)(g_Xg + (size_t)r * CC + k) = pk;
}

// ============ GEMM1 (R11-proven): 128x128 CTA, BK=32, Bf32 staging ============
#define ASTRH 40      // A row stride (halves) for BK=32
#define BSTRH 136     // B fp16 row stride (halves), BN=128

__global__ __launch_bounds__(256, 2)
void gemm1_mma(const float* __restrict__ Bw, const float* __restrict__ bias) {
    constexpr int BK  = 32;
    constexpr int NKC = CC / BK;                 // 32
    constexpr int MI  = 4, NI = 4;
    constexpr int AB  = 128 * ASTRH * 2;
    constexpr int BHB = 32 * BSTRH * 2;
    constexpr int BFB = 32 * 128 * 4;
    constexpr int A_OFF = 0, BH_OFF = 3 * AB, BF_OFF = BH_OFF + 3 * BHB;

    extern __shared__ char smem[];
    int tid = threadIdx.x, lane = tid & 31, wid = tid >> 5;
    int wm0 = (wid & 1) * 64;
    int wn0 = (wid >> 1) * 32;

    int m0 = blockIdx.x * 128;
    int n0 = blockIdx.y * 128;
    if (m0 >= g_off[NE]) return;
    int e = 0;
    #pragma unroll
    for (int i = 1; i < NE; i++) if (m0 >= g_off[i]) e = i;
    if (m0 >= g_off[e] + g_counts[e]) return;

    const __half* Abase = g_Xg + (size_t)m0 * CC;
    const float*  Bbase = Bw + (size_t)e * CC * HH + n0;

    uint32_t sbase = (uint32_t)__cvta_generic_to_shared(smem);

    auto cpA = [&](int stg, int k0) {
        uint32_t sA = sbase + (uint32_t)(A_OFF + stg * AB);
        #pragma unroll
        for (int it = 0; it < 2; it++) {
            int idx = it * 256 + tid;
            int r = idx >> 2, j = idx & 3;
            CP16(sA + (uint32_t)(r * ASTRH + j * 8) * 2u,
                 Abase + (size_t)r * CC + k0 + j * 8);
        }
    };
    auto cpBf = [&](int stg, int k0) {
        uint32_t sF = sbase + (uint32_t)(BF_OFF + stg * BFB);
        #pragma unroll
        for (int it = 0; it < 4; it++) {
            int idx = it * 256 + tid;
            int k = idx >> 5, c = idx & 31;
            CP16(sF + (uint32_t)(k * 128 + c * 4) * 4u,
                 Bbase + (size_t)(k0 + k) * HH + c * 4);
        }
    };
    auto cvtB = [&](int stg) {
        const float* src = (const float*)(smem + BF_OFF + stg * BFB);
        __half* dst = (__half*)(smem + BH_OFF + stg * BHB);
        #pragma unroll
        for (int it = 0; it < 4; it++) {
            int idx = it * 256 + tid;
            int k = idx >> 5, c = idx & 31;
            float4 v = *(const float4*)(src + k * 128 + c * 4);
            __half2 h0 = __floats2half2_rn(v.x, v.y);
            __half2 h1 = __floats2half2_rn(v.z, v.w);
            *(uint2*)(dst + k * BSTRH + c * 4) =
                make_uint2(*(uint32_t*)&h0, *(uint32_t*)&h1);
        }
    };

    float acc[MI][NI][4];
    #pragma unroll
    for (int mi = 0; mi < MI; mi++)
        #pragma unroll
        for (int ni = 0; ni < NI; ni++)
            #pragma unroll
            for (int q = 0; q < 4; q++) acc[mi][ni][q] = 0.f;

    uint32_t aoff[MI], boff;
    #pragma unroll
    for (int mi = 0; mi < MI; mi++)
        aoff[mi] = (uint32_t)((wm0 + mi * 16 + (lane & 15)) * ASTRH) * 2u
                 + (uint32_t)((lane >> 4) * 16);
    boff = (uint32_t)((lane & 15) * BSTRH) * 2u + (uint32_t)(wn0 * 2);

    cpBf(0, 0);        CPCOMMIT();
    cpA(0, 0);         CPCOMMIT();
    cpBf(1, BK);       CPCOMMIT();
    cpA(1, BK);        CPCOMMIT();
    cpBf(2, 2 * BK);   CPCOMMIT();
    CPWAIT4();
    __syncthreads();
    cvtB(0);

    for (int i = 0; i < NKC; i++) {
        CPWAIT2();
        __syncthreads();
        if (i + 1 < NKC) cvtB((i + 1) % 3);
        if (i + 3 < NKC) cpBf((i + 3) % 3, (i + 3) * BK);
        CPCOMMIT();
        if (i + 2 < NKC) cpA((i + 2) % 3, (i + 2) * BK);
        CPCOMMIT();

        uint32_t sA  = sbase + (uint32_t)(A_OFF + (i % 3) * AB);
        uint32_t sBh = sbase + (uint32_t)(BH_OFF + (i % 3) * BHB);
        #pragma unroll
        for (int ks = 0; ks < 2; ks++) {
            uint32_t af[MI][4], bf[NI][2];
            #pragma unroll
            for (int mi = 0; mi < MI; mi++)
                ldsm_x4(sA + aoff[mi] + (uint32_t)(ks * 32),
                        af[mi][0], af[mi][1], af[mi][2], af[mi][3]);
            #pragma unroll
            for (int ni = 0; ni < NI; ni++)
                ldsm_x2t(sBh + boff + (uint32_t)(ks * 16 * BSTRH * 2 + ni * 16),
                         bf[ni][0], bf[ni][1]);
            #pragma unroll
            for (int mi = 0; mi < MI; mi++)
                #pragma unroll
                for (int ni = 0; ni < NI; ni++)
                    mma_f16(acc[mi][ni], af[mi], bf[ni]);
        }
    }

    #pragma unroll
    for (int mi = 0; mi < MI; mi++) {
        int r0 = m0 + wm0 + mi * 16 + (lane >> 2);
        #pragma unroll
        for (int ni = 0; ni < NI; ni++) {
            int c = n0 + wn0 + ni * 8 + ((lane & 3) << 1);
            float bsv0 = bias[(size_t)e * HH + c];
            float bsv1 = bias[(size_t)e * HH + c + 1];
            float v0 = acc[mi][ni][0] + bsv0;
            float v1 = acc[mi][ni][1] + bsv1;
            float v2 = acc[mi][ni][2] + bsv0;
            float v3 = acc[mi][ni][3] + bsv1;
            v0 = 0.5f * v0 * (1.0f + erff(v0 * 0.70710678118654752f));
            v1 = 0.5f * v1 * (1.0f + erff(v1 * 0.70710678118654752f));
            v2 = 0.5f * v2 * (1.0f + erff(v2 * 0.70710678118654752f));
            v3 = 0.5f * v3 * (1.0f + erff(v3 * 0.70710678118654752f));
            __half2 h01 = __floats2half2_rn(v0, v1);
            __half2 h23 = __floats2half2_rn(v2, v3);
            *(uint32_t*)(g_H + (size_t)r0 * HH + c)       = *(uint32_t*)&h01;
            *(uint32_t*)(g_H + (size_t)(r0 + 8) * HH + c) = *(uint32_t*)&h23;
        }
    }
}

// ============ GEMM2 (new): 64x128 CTA, BK=64, register-carried B ============
// 8 warps (2m x 4n), warp 32x32, 4 k16-steps/iter -> 32 MMA/warp/iter.
// NKC = 64 (vs 128 at BK=32): halves per-iteration overhead exposure.
#define ASTRH2 72     // A row stride (halves) for BK=64 (64+8)

__global__ __launch_bounds__(256, 2)
void gemm2_mma(const float* __restrict__ Bw, const float* __restrict__ bias,
               float* __restrict__ outp) {
    constexpr int BK  = 64;
    constexpr int NKC = HH / BK;                 // 64
    constexpr int MI  = 2, NI = 4;
    constexpr int AB  = 64 * ASTRH2 * 2;         // 9216
    constexpr int BHB = 64 * BSTRH * 2;          // 17408
    constexpr int A_OFF = 0, BH_OFF = 3 * AB;

    extern __shared__ char smem[];
    int tid = threadIdx.x, lane = tid & 31, wid = tid >> 5;
    int wm0 = (wid & 1) * 32;
    int wn0 = (wid >> 1) * 32;

    int m0 = blockIdx.x * 64;
    int n0 = blockIdx.y * 128;
    if (m0 >= g_off[NE]) return;
    int e = 0;
    #pragma unroll
    for (int i = 1; i < NE; i++) if (m0 >= g_off[i]) e = i;
    if (m0 >= g_off[e] + g_counts[e]) return;

    const __half* Abase = g_H + (size_t)m0 * HH;
    const float*  Bbase = Bw + (size_t)e * HH * CC + n0;

    uint32_t sbase = (uint32_t)__cvta_generic_to_shared(smem);

    auto cpA = [&](int stg, int k0) {            // 64 rows x 64 halves = 512 chunks
        uint32_t sA = sbase + (uint32_t)(A_OFF + stg * AB);
        #pragma unroll
        for (int it = 0; it < 2; it++) {
            int idx = it * 256 + tid;
            int r = idx >> 3, j = idx & 7;
            CP16(sA + (uint32_t)(r * ASTRH2 + j * 8) * 2u,
                 Abase + (size_t)r * HH + k0 + j * 8);
        }
    };
    float4 fB[8];                                // 64 k x 128 n fp32 = 8 f4/thread
    auto ldgB = [&](int k0) {
        #pragma unroll
        for (int it = 0; it < 8; it++) {
            int idx = it * 256 + tid;
            int k = idx >> 5, c = idx & 31;
            fB[it] = *(const float4*)(Bbase + (size_t)(k0 + k) * CC + c * 4);
        }
    };
    auto stsB = [&](int stg) {
        uint32_t sB = sbase + (uint32_t)(BH_OFF + stg * BHB);
        #pragma unroll
        for (int it = 0; it < 8; it++) {
            int idx = it * 256 + tid;
            int k = idx >> 5, c = idx & 31;
            __half2 h0 = __floats2half2_rn(fB[it].x, fB[it].y);
            __half2 h1 = __floats2half2_rn(fB[it].z, fB[it].w);
            STS64(sB + (uint32_t)(k * BSTRH + c * 4) * 2u,
                  *(uint32_t*)&h0, *(uint32_t*)&h1);
        }
    };

    float acc[MI][NI][4];
    #pragma unroll
    for (int mi = 0; mi < MI; mi++)
        #pragma unroll
        for (int ni = 0; ni < NI; ni++)
            #pragma unroll
            for (int q = 0; q < 4; q++) acc[mi][ni][q] = 0.f;

    uint32_t aoff[MI], boff;
    #pragma unroll
    for (int mi = 0; mi < MI; mi++)
        aoff[mi] = (uint32_t)((wm0 + mi * 16 + (lane & 15)) * ASTRH2) * 2u
                 + (uint32_t)((lane >> 4) * 16);
    boff = (uint32_t)((lane & 15) * BSTRH) * 2u + (uint32_t)(wn0 * 2);

    // prologue: A(0),A(1) in flight; Bh(0) staged; fB holds B(1)
    ldgB(0);
    cpA(0, 0);  CPCOMMIT();
    cpA(1, BK); CPCOMMIT();
    stsB(0);
    ldgB(BK);

    for (int i = 0; i < NKC; i++) {
        CPWAIT1();                    // A(i) resident
        __syncthreads();              // orders stsB(i) + ring-slot drain
        if (i + 1 < NKC) stsB((i + 1) % 3);      // from fB (no stall)
        if (i + 2 < NKC) {
            ldgB((i + 2) * BK);       // hidden under this iter's MMAs
            cpA((i + 2) % 3, (i + 2) * BK);
        }
        CPCOMMIT();

        uint32_t sA  = sbase + (uint32_t)(A_OFF + (i % 3) * AB);
        uint32_t sBh = sbase + (uint32_t)(BH_OFF + (i % 3) * BHB);
        #pragma unroll
        for (int ks = 0; ks < 4; ks++) {
            uint32_t af[MI][4], bf[NI][2];
            #pragma unroll
            for (int mi = 0; mi < MI; mi++)
                ldsm_x4(sA + aoff[mi] + (uint32_t)(ks * 32),
                        af[mi][0], af[mi][1], af[mi][2], af[mi][3]);
            #pragma unroll
            for (int ni = 0; ni < NI; ni++)
                ldsm_x2t(sBh + boff + (uint32_t)(ks * 16 * BSTRH * 2 + ni * 16),
                         bf[ni][0], bf[ni][1]);
            #pragma unroll
            for (int mi = 0; mi < MI; mi++)
                #pragma unroll
                for (int ni = 0; ni < NI; ni++)
                    mma_f16(acc[mi][ni], af[mi], bf[ni]);
        }
    }

    #pragma unroll
    for (int mi = 0; mi < MI; mi++) {
        int r0 = m0 + wm0 + mi * 16 + (lane >> 2);
        int tok0 = -1, tok1 = -1; float sc0 = 0.f, sc1 = 0.f;
        if ((r0 - g_off[e]) < g_counts[e])     { tok0 = g_perm[r0];     sc0 = g_score[tok0]; }
        if ((r0 + 8 - g_off[e]) < g_counts[e]) { tok1 = g_perm[r0 + 8]; sc1 = g_score[tok1]; }
        #pragma unroll
        for (int ni = 0; ni < NI; ni++) {
            int c = n0 + wn0 + ni * 8 + ((lane & 3) << 1);
            float bsv0 = bias[(size_t)e * CC + c];
            float bsv1 = bias[(size_t)e * CC + c + 1];
            if (tok0 >= 0) {
                float v0 = (acc[mi][ni][0] + bsv0) * sc0;
                float v1 = (acc[mi][ni][1] + bsv1) * sc0;
                *(float2*)(outp + (size_t)tok0 * CC + c) = make_float2(v0, v1);
            }
            if (tok1 >= 0) {
                float v2 = (acc[mi][ni][2] + bsv0) * sc1;
                float v3 = (acc[mi][ni][3] + bsv1) * sc1;
                *(float2*)(outp + (size_t)tok1 * CC + c) = make_float2(v2, v3);
            }
        }
    }
}

// smem bytes
#define SM1 (3 * (128 * ASTRH * 2 + 32 * BSTRH * 2 + 32 * 128 * 4))   // 105984
#define SM2 (3 * (64 * ASTRH2 * 2 + 64 * BSTRH * 2))                  // 79872

// ---------------- launch ----------------
extern "C" void kernel_launch(void* const* d_in, const int* in_sizes, int n_in,
                              void* d_out, int out_size) {
    const float* x      = (const float*)d_in[0];
    const float* wg_red = (const float*)d_in[1];
    const float* wg     = (const float*)d_in[2];
    const float* w1     = (const float*)d_in[3];
    const float* b1     = (const float*)d_in[4];
    const float* w2     = (const float*)d_in[5];
    const float* b2     = (const float*)d_in[6];
    float* out = (float*)d_out;

    cudaFuncSetAttribute(gemm1_mma, cudaFuncAttributeMaxDynamicSharedMemorySize, SM1);
    cudaFuncSetAttribute(gemm2_mma, cudaFuncAttributeMaxDynamicSharedMemorySize, SM2);

    gate_kernel<<<TT / 8, 256>>>(x, wg_red, wg);          // launch 0
    offs_scatter_kernel<<<1, 256>>>();                    // launch 1
    gather_kernel<<<RCAP, 256>>>(x);                      // launch 2
    gemm1_mma<<<dim3(RCAP / 128, HH / 128), 256, SM1>>>(w1, b1);   // launch 3
    gemm2_mma<<<dim3(RCAP / 64, CC / 128), 256, SM2>>>(w2, b2, out); // launch 4
}